// round 10
// baseline (speedup 1.0000x reference)
#include <cuda_runtime.h>
#include <cstdint>

#define DIMZ 96
#define OUT_ROW 4753            // 1 + 96 + 96*97/2
#define G 4                     // rows per CTA
#define TPB 256
#define NVEC 4753               // float4s per CTA superblock (G*OUT_ROW/4)
#define NSEG (G * 97)           // 388 zext-segments per superblock
#define CST 392                 // rotated-copy stride in words (mult of 8)

// Per-float4 descriptor: bits 0..12 = byte offset of zj LDS.128 (rotated copy
// folded in), bits 13..23 = byte offset of zi, bit 31 = crossing flag
// (crossing slots redirect their store to the dump buffer; fixup writes them).
__device__ uint32_t g_ab[NVEC];
// Compacted crossing list: x = v | (p<<13), y = a | (b<<10)  (word indices).
__device__ uint2 g_cross[1024];
__device__ int   g_ncross;
// L2-resident garbage sink: 64 rotating 4KB slabs.
__device__ float4 g_dump[64 * TPB];

// flat zext-pair of superblock-local element l (closed form + integer fixup)
__device__ __forceinline__ void elem_ab(int l, int& a, int& b) {
    int r = l / OUT_ROW;
    int k = l - r * OUT_ROW;
    int base = r * 97;
    if (k < 97) { a = base; b = base + k; return; }
    int q = k - 97;
    int i = (int)((193.0f - sqrtf((float)(37249 - 8 * q))) * 0.5f);
    if (i < 0) i = 0;
    while (i > 0 && (i * 96 - (i * (i - 1)) / 2) > q) --i;
    while (((i + 1) * 96 - ((i + 1) * i) / 2) <= q) ++i;
    int acc = i * 96 - (i * (i - 1)) / 2;
    int j = i + (q - acc);
    a = base + i + 1;
    b = base + j + 1;
}

// Single merged init: all blocks fill g_ab; block 0 also builds the crossing list.
__global__ __launch_bounds__(512) void init_kernel() {
    const int t = threadIdx.x;
    const int v = blockIdx.x * 512 + t;

    if (v < NVEC) {
        int a0, b0, a3, b3;
        elem_ab(4 * v, a0, b0);
        elem_ab(4 * v + 3, a3, b3);
        int c = b0 & 3;
        uint32_t zjb = (uint32_t)(4 * (c * CST + (b0 - c)));  // 13 bits
        uint32_t ab  = (uint32_t)(4 * a0);                    // 11 bits
        uint32_t d = zjb | (ab << 13);
        if (a3 != a0) d |= 0x80000000u;                       // crossing flag
        g_ab[v] = d;
    }

    if (blockIdx.x != 0) return;

    __shared__ int sc[512];
    int E = 0, L = 0, cf = 0;
    if (t < NSEG) {
        int r = t / 97, s = t - r * 97;
        int Srow = 97 * s - (s * (s - 1)) / 2;
        E = r * OUT_ROW + Srow;
        L = 97 - s;
        int End = E + L;
        if (End & 3) {
            int Lnext = (s < 96) ? (96 - s) : 97;
            if (((End + Lnext) >> 2) > (End >> 2)) cf = 1;  // this seg owns v
        }
    }
    sc[t] = cf;
    __syncthreads();
    for (int d = 1; d < 512; d <<= 1) {
        int x = sc[t];
        if (t >= d) x += sc[t - d];
        __syncthreads();
        sc[t] = x;
        __syncthreads();
    }
    if (t == 0) g_ncross = sc[511];

    if (t < NSEG && cf) {
        int cidx = sc[t] - 1;
        int vx = (E + L) >> 2;
        int a[4], b[4];
        #pragma unroll
        for (int e = 0; e < 4; e++) elem_ab(4 * vx + e, a[e], b[e]);
        uint32_t p = 0;
        if (a[1] != a[0]) p |= 1u;
        if (a[2] != a[1]) p |= 2u;
        if (a[3] != a[2]) p |= 4u;
        uint2 ent;
        ent.x = (uint32_t)vx | (p << 13);
        ent.y = (uint32_t)a[0] | ((uint32_t)b[0] << 10);
        g_cross[cidx] = ent;
    }
}

__global__ __launch_bounds__(TPB) void poly_kernel(const float* __restrict__ z,
                                                   float* __restrict__ out) {
    // 4 rotated copies of zext: zsh[c*CST + x] = zext(x + c), zero-padded.
    // zext(y): y%97==0 -> 1.0, else z_row[y%97 - 1], rows concatenated.
    __shared__ float zsh[4 * CST];

    const int tid = threadIdx.x;
    const float* zr = z + (size_t)blockIdx.x * (G * DIMZ);

    for (int w = tid; w < 4 * CST; w += TPB) {
        int c = w / CST;
        int x = w - c * CST;
        int y = x + c;
        float val = 0.0f;
        if (y < NSEG) {
            int row = y / 97, pos = y - row * 97;
            val = (pos == 0) ? 1.0f : zr[row * DIMZ + pos - 1];
        }
        zsh[w] = val;
    }
    __syncthreads();

    float4* o4 = (float4*)(out + (size_t)blockIdx.x * (G * OUT_ROW));
    const char* zb8 = (const char*)zsh;
    float4* dump = &g_dump[(blockIdx.x & 63) * TPB + tid];

    // ---- main loop: branch-free; crossing slots store to the L2 dump ----
    #pragma unroll 4
    for (int v = tid; v < NVEC; v += TPB) {
        const uint32_t d = __ldg(&g_ab[v]);
        const float4 zj = *(const float4*)(zb8 + (d & 0x1FFFu));
        const float  zi = *(const float*)(zb8 + ((d >> 13) & 0x7FFu));
        float4 res;
        res.x = zi * zj.x;
        res.y = zi * zj.y;
        res.z = zi * zj.z;
        res.w = zi * zj.w;
        // unconditional store; address selected by flag (SEL, no branch/predicate)
        float4* dst = (d & 0x80000000u) ? dump : &o4[v];
        __stcs(dst, res);
    }

    // fixup is the sole writer of crossing output slots -> no barrier needed

    // ---- fixup: write the ~291 segment-crossing float4s ----
    const int nc = g_ncross;
    for (int s = tid; s < nc; s += TPB) {
        const uint2 e = __ldg(&g_cross[s]);
        const int v = e.x & 0x1FFF;
        const uint32_t p = e.x >> 13;
        int a = e.y & 1023;
        int b = (e.y >> 10) & 1023;
        float4 res;
        res.x = zsh[a] * zsh[b];
        a += (p & 1u);        b = (p & 1u) ? a : (b + 1);
        res.y = zsh[a] * zsh[b];
        a += ((p >> 1) & 1u); b = ((p >> 1) & 1u) ? a : (b + 1);
        res.z = zsh[a] * zsh[b];
        a += ((p >> 2) & 1u); b = ((p >> 2) & 1u) ? a : (b + 1);
        res.w = zsh[a] * zsh[b];
        __stcs(&o4[v], res);
    }
}

extern "C" void kernel_launch(void* const* d_in, const int* in_sizes, int n_in,
                              void* d_out, int out_size) {
    const float* z = (const float*)d_in[0];
    float* out = (float*)d_out;
    const int B = in_sizes[0] / DIMZ;   // 32768, divisible by G=4

    init_kernel<<<10, 512>>>();
    poly_kernel<<<B / G, TPB>>>(z, out);
}

// round 11
// speedup vs baseline: 1.7405x; 1.7405x over previous
#include <cuda_runtime.h>
#include <cstdint>

#define DIMZ 96
#define OUT_ROW 4753            // 1 + 96 + 96*97/2
#define G 4                     // rows per CTA
#define TPB 256
#define NVEC 4753               // float4s per CTA superblock (G*OUT_ROW/4)
#define NSEG (G * 97)           // 388 zext-segments per superblock
#define CST 392                 // rotated-copy stride in words (mult of 8)

// Per-float4 descriptor: bits 0..12 = byte offset of zj LDS.128 (rotated copy
// folded in), bits 13..23 = byte offset of zi. Crossing slots hold garbage and
// are overwritten by the fixup loop after the barrier.
__device__ uint32_t g_ab[NVEC];
// Compacted crossing list: x = v | (p<<13), y = a | (b<<10)  (word indices).
__device__ uint2 g_cross[1024];
__device__ int   g_ncross;

// flat zext-pair of superblock-local element l (closed form + integer fixup)
__device__ __forceinline__ void elem_ab(int l, int& a, int& b) {
    int r = l / OUT_ROW;
    int k = l - r * OUT_ROW;
    int base = r * 97;
    if (k < 97) { a = base; b = base + k; return; }
    int q = k - 97;
    int i = (int)((193.0f - sqrtf((float)(37249 - 8 * q))) * 0.5f);
    if (i < 0) i = 0;
    while (i > 0 && (i * 96 - (i * (i - 1)) / 2) > q) --i;
    while (((i + 1) * 96 - ((i + 1) * i) / 2) <= q) ++i;
    int acc = i * 96 - (i * (i - 1)) / 2;
    int j = i + (q - acc);
    a = base + i + 1;
    b = base + j + 1;
}

// Single merged init: all blocks fill g_ab; block 0 also builds the crossing list.
__global__ __launch_bounds__(512) void init_kernel() {
    const int t = threadIdx.x;
    const int v = blockIdx.x * 512 + t;

    if (v < NVEC) {
        int a0, b0;
        elem_ab(4 * v, a0, b0);
        int c = b0 & 3;
        uint32_t zjb = (uint32_t)(4 * (c * CST + (b0 - c)));  // 13 bits
        uint32_t ab  = (uint32_t)(4 * a0);                    // 11 bits
        g_ab[v] = zjb | (ab << 13);
    }

    if (blockIdx.x != 0) return;

    __shared__ int sc[512];
    int E = 0, L = 0, cf = 0;
    if (t < NSEG) {
        int r = t / 97, s = t - r * 97;
        int Srow = 97 * s - (s * (s - 1)) / 2;
        E = r * OUT_ROW + Srow;
        L = 97 - s;
        int End = E + L;
        if (End & 3) {
            int Lnext = (s < 96) ? (96 - s) : 97;
            if (((End + Lnext) >> 2) > (End >> 2)) cf = 1;  // this seg owns v
        }
    }
    sc[t] = cf;
    __syncthreads();
    for (int d = 1; d < 512; d <<= 1) {
        int x = sc[t];
        if (t >= d) x += sc[t - d];
        __syncthreads();
        sc[t] = x;
        __syncthreads();
    }
    if (t == 0) g_ncross = sc[511];

    if (t < NSEG && cf) {
        int cidx = sc[t] - 1;
        int vx = (E + L) >> 2;
        int a[4], b[4];
        #pragma unroll
        for (int e = 0; e < 4; e++) elem_ab(4 * vx + e, a[e], b[e]);
        uint32_t p = 0;
        if (a[1] != a[0]) p |= 1u;
        if (a[2] != a[1]) p |= 2u;
        if (a[3] != a[2]) p |= 4u;
        uint2 ent;
        ent.x = (uint32_t)vx | (p << 13);
        ent.y = (uint32_t)a[0] | ((uint32_t)b[0] << 10);
        g_cross[cidx] = ent;
    }
}

__global__ __launch_bounds__(TPB) void poly_kernel(const float* __restrict__ z,
                                                   float* __restrict__ out) {
    // 4 rotated copies of zext: zsh[c*CST + x] = zext(x + c), zero-padded.
    // zext(y): y%97==0 -> 1.0, else z_row[y%97 - 1], rows concatenated.
    __shared__ float zsh[4 * CST];

    const int tid = threadIdx.x;
    const float* zr = z + (size_t)blockIdx.x * (G * DIMZ);

    for (int w = tid; w < 4 * CST; w += TPB) {
        int c = w / CST;
        int x = w - c * CST;
        int y = x + c;
        float val = 0.0f;
        if (y < NSEG) {
            int row = y / 97, pos = y - row * 97;
            val = (pos == 0) ? 1.0f : zr[row * DIMZ + pos - 1];
        }
        zsh[w] = val;
    }
    __syncthreads();

    float4* o4 = (float4*)(out + (size_t)blockIdx.x * (G * OUT_ROW));
    const char* zb8 = (const char*)zsh;

    // ---- main loop: branch-free, fully unconditional (R8 shape, deeper unroll).
    // Crossing slots get garbage here; fixed up after the barrier. ----
    #pragma unroll 8
    for (int v = tid; v < NVEC; v += TPB) {
        const uint32_t d = __ldg(&g_ab[v]);
        const float4 zj = *(const float4*)(zb8 + (d & 0x1FFFu));
        const float  zi = *(const float*)(zb8 + (d >> 13));
        float4 res;
        res.x = zi * zj.x;
        res.y = zi * zj.y;
        res.z = zi * zj.z;
        res.w = zi * zj.w;
        __stcs(&o4[v], res);               // streaming, unconditional
    }

    // Barrier orders all main-loop stores before the fixup overwrites.
    __syncthreads();

    // ---- fixup: overwrite the ~291 segment-crossing float4s ----
    const int nc = g_ncross;
    for (int s = tid; s < nc; s += TPB) {
        const uint2 e = __ldg(&g_cross[s]);
        const int v = e.x & 0x1FFF;
        const uint32_t p = e.x >> 13;
        int a = e.y & 1023;
        int b = (e.y >> 10) & 1023;
        float4 res;
        res.x = zsh[a] * zsh[b];
        a += (p & 1u);        b = (p & 1u) ? a : (b + 1);
        res.y = zsh[a] * zsh[b];
        a += ((p >> 1) & 1u); b = ((p >> 1) & 1u) ? a : (b + 1);
        res.z = zsh[a] * zsh[b];
        a += ((p >> 2) & 1u); b = ((p >> 2) & 1u) ? a : (b + 1);
        res.w = zsh[a] * zsh[b];
        __stcs(&o4[v], res);
    }
}

extern "C" void kernel_launch(void* const* d_in, const int* in_sizes, int n_in,
                              void* d_out, int out_size) {
    const float* z = (const float*)d_in[0];
    float* out = (float*)d_out;
    const int B = in_sizes[0] / DIMZ;   // 32768, divisible by G=4

    init_kernel<<<10, 512>>>();
    poly_kernel<<<B / G, TPB>>>(z, out);
}

// round 12
// speedup vs baseline: 1.7670x; 1.0153x over previous
#include <cuda_runtime.h>
#include <cstdint>

#define DIMZ 96
#define OUT_ROW 4753            // 1 + 96 + 96*97/2
#define G 4                     // rows per CTA
#define TPB 256
#define NVEC 4753               // float4s per CTA superblock (G*OUT_ROW/4)
#define NSEG (G * 97)           // 388 zext-segments per superblock
#define CST 392                 // rotated-copy stride in words (mult of 8)
#define NPAIRIT 9               // paired iterations: 9*512 = 4608 v's
#define VTAIL (NPAIRIT * 2 * TPB)  // 4608

// Scalar descriptor (tail + reference): bits 0..12 = byte offset of zj LDS.128
// (rotated copy folded in), bits 13..23 = byte offset of zi.
__device__ uint32_t g_ab[NVEC];
// Paired table: entry p = m*TPB + t holds {desc(m*512+t), desc(m*512+t+256)}.
__device__ uint2 g_ab2[NPAIRIT * TPB];
// Compacted crossing list: x = v | (p<<13), y = a | (b<<10)  (word indices).
__device__ uint2 g_cross[1024];
__device__ int   g_ncross;

// flat zext-pair of superblock-local element l (closed form + integer fixup)
__device__ __forceinline__ void elem_ab(int l, int& a, int& b) {
    int r = l / OUT_ROW;
    int k = l - r * OUT_ROW;
    int base = r * 97;
    if (k < 97) { a = base; b = base + k; return; }
    int q = k - 97;
    int i = (int)((193.0f - sqrtf((float)(37249 - 8 * q))) * 0.5f);
    if (i < 0) i = 0;
    while (i > 0 && (i * 96 - (i * (i - 1)) / 2) > q) --i;
    while (((i + 1) * 96 - ((i + 1) * i) / 2) <= q) ++i;
    int acc = i * 96 - (i * (i - 1)) / 2;
    int j = i + (q - acc);
    a = base + i + 1;
    b = base + j + 1;
}

__device__ __forceinline__ uint32_t make_desc(int v) {
    int a0, b0;
    elem_ab(4 * v, a0, b0);
    int c = b0 & 3;
    uint32_t zjb = (uint32_t)(4 * (c * CST + (b0 - c)));  // 13 bits
    uint32_t ab  = (uint32_t)(4 * a0);                    // 11 bits
    return zjb | (ab << 13);
}

// Single merged init: all blocks fill tables; block 0 also builds crossing list.
__global__ __launch_bounds__(512) void init_kernel() {
    const int t = threadIdx.x;
    const int v = blockIdx.x * 512 + t;

    if (v < NVEC) g_ab[v] = make_desc(v);

    // paired table (2304 entries)
    const int p = blockIdx.x * 512 + t;
    if (p < NPAIRIT * TPB) {
        int m  = p / TPB;
        int tt = p - m * TPB;
        int v0 = m * 2 * TPB + tt;
        uint2 e;
        e.x = make_desc(v0);
        e.y = make_desc(v0 + TPB);
        g_ab2[p] = e;
    }

    if (blockIdx.x != 0) return;

    __shared__ int sc[512];
    int E = 0, L = 0, cf = 0;
    if (t < NSEG) {
        int r = t / 97, s = t - r * 97;
        int Srow = 97 * s - (s * (s - 1)) / 2;
        E = r * OUT_ROW + Srow;
        L = 97 - s;
        int End = E + L;
        if (End & 3) {
            int Lnext = (s < 96) ? (96 - s) : 97;
            if (((End + Lnext) >> 2) > (End >> 2)) cf = 1;  // this seg owns v
        }
    }
    sc[t] = cf;
    __syncthreads();
    for (int d = 1; d < 512; d <<= 1) {
        int x = sc[t];
        if (t >= d) x += sc[t - d];
        __syncthreads();
        sc[t] = x;
        __syncthreads();
    }
    if (t == 0) g_ncross = sc[511];

    if (t < NSEG && cf) {
        int cidx = sc[t] - 1;
        int vx = (E + L) >> 2;
        int a[4], b[4];
        #pragma unroll
        for (int e = 0; e < 4; e++) elem_ab(4 * vx + e, a[e], b[e]);
        uint32_t p2 = 0;
        if (a[1] != a[0]) p2 |= 1u;
        if (a[2] != a[1]) p2 |= 2u;
        if (a[3] != a[2]) p2 |= 4u;
        uint2 ent;
        ent.x = (uint32_t)vx | (p2 << 13);
        ent.y = (uint32_t)a[0] | ((uint32_t)b[0] << 10);
        g_cross[cidx] = ent;
    }
}

__global__ __launch_bounds__(TPB) void poly_kernel(const float* __restrict__ z,
                                                   float* __restrict__ out) {
    // 4 rotated copies of zext: zsh[c*CST + x] = zext(x + c), zero-padded.
    // zext(y): y%97==0 -> 1.0, else z_row[y%97 - 1], rows concatenated.
    __shared__ float zsh[4 * CST];

    const int tid = threadIdx.x;
    const float* zr = z + (size_t)blockIdx.x * (G * DIMZ);

    for (int w = tid; w < 4 * CST; w += TPB) {
        int c = w / CST;
        int x = w - c * CST;
        int y = x + c;
        float val = 0.0f;
        if (y < NSEG) {
            int row = y / 97, pos = y - row * 97;
            val = (pos == 0) ? 1.0f : zr[row * DIMZ + pos - 1];
        }
        zsh[w] = val;
    }
    __syncthreads();

    float4* o4 = (float4*)(out + (size_t)blockIdx.x * (G * OUT_ROW));
    const char* zb8 = (const char*)zsh;

    // ---- main loop: paired, branch-free, fully unconditional.
    // Crossing slots get garbage; fixed up after the barrier. ----
    #pragma unroll 4
    for (int m = 0; m < NPAIRIT; m++) {
        const uint2 dd = __ldg(&g_ab2[m * TPB + tid]);
        const int v0 = m * 2 * TPB + tid;

        const float4 zj0 = *(const float4*)(zb8 + (dd.x & 0x1FFFu));
        const float  zi0 = *(const float*)(zb8 + (dd.x >> 13));
        const float4 zj1 = *(const float4*)(zb8 + (dd.y & 0x1FFFu));
        const float  zi1 = *(const float*)(zb8 + (dd.y >> 13));

        float4 r0, r1;
        r0.x = zi0 * zj0.x; r0.y = zi0 * zj0.y;
        r0.z = zi0 * zj0.z; r0.w = zi0 * zj0.w;
        r1.x = zi1 * zj1.x; r1.y = zi1 * zj1.y;
        r1.z = zi1 * zj1.z; r1.w = zi1 * zj1.w;

        __stcs(&o4[v0], r0);
        __stcs(&o4[v0 + TPB], r1);
    }

    // ---- scalar tail: v in [4608, 4753) ----
    for (int v = VTAIL + tid; v < NVEC; v += TPB) {
        const uint32_t d = __ldg(&g_ab[v]);
        const float4 zj = *(const float4*)(zb8 + (d & 0x1FFFu));
        const float  zi = *(const float*)(zb8 + (d >> 13));
        float4 res;
        res.x = zi * zj.x;
        res.y = zi * zj.y;
        res.z = zi * zj.z;
        res.w = zi * zj.w;
        __stcs(&o4[v], res);
    }

    // Barrier orders all main-loop stores before the fixup overwrites.
    __syncthreads();

    // ---- fixup: overwrite the ~291 segment-crossing float4s ----
    const int nc = g_ncross;
    for (int s = tid; s < nc; s += TPB) {
        const uint2 e = __ldg(&g_cross[s]);
        const int v = e.x & 0x1FFF;
        const uint32_t p = e.x >> 13;
        int a = e.y & 1023;
        int b = (e.y >> 10) & 1023;
        float4 res;
        res.x = zsh[a] * zsh[b];
        a += (p & 1u);        b = (p & 1u) ? a : (b + 1);
        res.y = zsh[a] * zsh[b];
        a += ((p >> 1) & 1u); b = ((p >> 1) & 1u) ? a : (b + 1);
        res.z = zsh[a] * zsh[b];
        a += ((p >> 2) & 1u); b = ((p >> 2) & 1u) ? a : (b + 1);
        res.w = zsh[a] * zsh[b];
        __stcs(&o4[v], res);
    }
}

extern "C" void kernel_launch(void* const* d_in, const int* in_sizes, int n_in,
                              void* d_out, int out_size) {
    const float* z = (const float*)d_in[0];
    float* out = (float*)d_out;
    const int B = in_sizes[0] / DIMZ;   // 32768, divisible by G=4

    init_kernel<<<10, 512>>>();
    poly_kernel<<<B / G, TPB>>>(z, out);
}